// round 10
// baseline (speedup 1.0000x reference)
#include <cuda_runtime.h>
#include <cuda_bf16.h>

// values[m] = sum_n exp(-0.5 * sum_d (p[m,d]-pos[n,d])^2 / (exp(ls[n,d])^2+eps)) * I[n]
//
// Log2-domain expansion per gaussian n:
//   civ_d = -0.5*log2(e)/(exp(ls_d)^2+eps)  (<= 0)
//   a_d=civ_d; b_d=-2*civ_d*s_d; cc = sum_d civ_d*s_d^2 + log2(I)
//   arg = sum_d (a_d*p_d^2 + b_d*p_d) + cc ; contribution = exp2(arg)
//
// SPATIAL CULLING: 8x8x8 cell grid over [0,1]^3. For a cell box and gaussian n,
// the max possible arg over the box is sum_d civ_d*boxdist_d^2 + log2(I).
// If that bound < CUT_ARG (=-37 -> contribution < 7e-12) the gaussian is
// dropped for that cell. With sigma=e^-3 this keeps ~15-20% of gaussians/cell.
//
// Pipeline (one CUDA graph, no allocations):
//   memset cell counters -> prep (coeffs + point binning) -> build per-cell
//   pair-packed coefficient lists (deterministic ballot compaction) ->
//   scan -> scatter-sort points by cell -> eval (FFMA2 pair inner loop,
//   grid = 512 cells x 2 gaussian-segments, atomicAdd combine).

#define GDIM   8
#define NCELLS (GDIM * GDIM * GDIM)      // 512
#define MAXM   65536
#define MAXNG  2048
#define MAXP   512                       // max pairs per cell
#define CUT_ARG (-37.0f)
#define EVAL_SEGS 2
#define EVAL_THREADS 128

__device__ float4 g_q0[MAXNG];           // (ax, ay, az, bx)
__device__ float4 g_q1[MAXNG];           // (by, bz, cc, log2I)
__device__ int    g_cellCount[NCELLS];
__device__ int    g_cellStart[NCELLS];
__device__ int    g_pCell[MAXM];
__device__ int    g_pSlot[MAXM];
__device__ int    g_sorted[MAXM];
__device__ int    g_cellPairCount[NCELLS];
__device__ float4 g_cellPairs[NCELLS * MAXP * 4];   // 16MB pair-packed coeffs

// ---------- packed f32x2 helpers ----------
__device__ __forceinline__ unsigned long long ffma2(unsigned long long a,
                                                    unsigned long long b,
                                                    unsigned long long c) {
    unsigned long long d;
    asm("fma.rn.f32x2 %0, %1, %2, %3;" : "=l"(d) : "l"(a), "l"(b), "l"(c));
    return d;
}
__device__ __forceinline__ unsigned long long addx2(unsigned long long a,
                                                    unsigned long long b) {
    unsigned long long d;
    asm("add.rn.f32x2 %0, %1, %2;" : "=l"(d) : "l"(a), "l"(b));
    return d;
}
__device__ __forceinline__ unsigned long long pack2(float lo, float hi) {
    unsigned long long d;
    asm("mov.b64 %0, {%1, %2};" : "=l"(d) : "f"(lo), "f"(hi));
    return d;
}
__device__ __forceinline__ float pair_hsum(unsigned long long v) {
    float lo, hi;
    asm("mov.b64 {%0, %1}, %2;" : "=f"(lo), "=f"(hi) : "l"(v));
    return lo + hi;
}
__device__ __forceinline__ void unpack2(unsigned long long v, float& lo, float& hi) {
    asm("mov.b64 {%0, %1}, %2;" : "=f"(lo), "=f"(hi) : "l"(v));
}
__device__ __forceinline__ float ex2(float x) {
    float r;
    asm("ex2.approx.f32 %0, %1;" : "=f"(r) : "f"(x));
    return r;
}

// ---------- K1: coefficients + zero out + bin points ----------
__global__ void prep_kernel(const float* __restrict__ points,
                            const float* __restrict__ positions,
                            const float* __restrict__ log_scales,
                            const float* __restrict__ intensities,
                            float* __restrict__ out,
                            int M, int N) {
    int idx = blockIdx.x * blockDim.x + threadIdx.x;
    if (idx < M) {
        out[idx] = 0.0f;
        float px = points[3 * idx], py = points[3 * idx + 1], pz = points[3 * idx + 2];
        int cx = min(GDIM - 1, max(0, (int)(px * GDIM)));
        int cy = min(GDIM - 1, max(0, (int)(py * GDIM)));
        int cz = min(GDIM - 1, max(0, (int)(pz * GDIM)));
        int cell = (cz * GDIM + cy) * GDIM + cx;
        g_pCell[idx] = cell;
        g_pSlot[idx] = atomicAdd(&g_cellCount[cell], 1);
    }
    if (idx < N) {
        const float LOG2E = 1.4426950408889634f;
        float a[3], b[3];
        float c = 0.0f;
#pragma unroll
        for (int d = 0; d < 3; d++) {
            float s = __expf(log_scales[3 * idx + d]);
            float civ = -0.5f * LOG2E / (s * s + 1e-6f);
            float p = positions[3 * idx + d];
            a[d] = civ;
            b[d] = -2.0f * civ * p;
            c = fmaf(civ, p * p, c);
        }
        float logI = __log2f(intensities[idx]);   // I=0 -> -inf -> culled/zero
        g_q0[idx] = make_float4(a[0], a[1], a[2], b[0]);
        g_q1[idx] = make_float4(b[1], b[2], c + logI, logI);
    }
}

// ---------- K2: per-cell culled pair lists (deterministic) ----------
__global__ void __launch_bounds__(256)
build_lists(const float* __restrict__ positions, int N) {
    __shared__ int list[MAXNG];
    __shared__ int wcount[8];
    __shared__ int woff[8];

    int cell = blockIdx.x;
    int cx = cell & (GDIM - 1);
    int cy = (cell >> 3) & (GDIM - 1);
    int cz = cell >> 6;
    const float W = 1.0f / GDIM;
    float lox = cx * W, hix = lox + W;
    float loy = cy * W, hiy = loy + W;
    float loz = cz * W, hiz = loz + W;

    int w = threadIdx.x >> 5;
    int lane = threadIdx.x & 31;
    int numChunks = (N + 31) >> 5;

    unsigned msk[8];
    int cntw = 0;
    int ki = 0;
    for (int c = w; c < numChunks; c += 8, ki++) {
        int n = c * 32 + lane;
        bool keep = false;
        if (n < N) {
            float4 q0 = g_q0[n];
            float logI = g_q1[n].w;
            float sx = positions[3 * n], sy = positions[3 * n + 1], sz = positions[3 * n + 2];
            float ddx = fmaxf(fmaxf(lox - sx, sx - hix), 0.0f);
            float ddy = fmaxf(fmaxf(loy - sy, sy - hiy), 0.0f);
            float ddz = fmaxf(fmaxf(loz - sz, sz - hiz), 0.0f);
            float bound = q0.x * ddx * ddx + q0.y * ddy * ddy + q0.z * ddz * ddz + logI;
            keep = (bound >= CUT_ARG);
        }
        unsigned mk = __ballot_sync(0xffffffffu, keep);
        msk[ki] = mk;
        cntw += __popc(mk);
    }
    if (lane == 0) wcount[w] = cntw;
    __syncthreads();
    if (threadIdx.x == 0) {
        int run = 0;
#pragma unroll
        for (int i = 0; i < 8; i++) { woff[i] = run; run += wcount[i]; }
    }
    __syncthreads();

    int off = woff[w];
    ki = 0;
    for (int c = w; c < numChunks; c += 8, ki++) {
        unsigned mk = msk[ki];
        int n = c * 32 + lane;
        if ((mk >> lane) & 1u) {
            int rank = __popc(mk & ((1u << lane) - 1u));
            list[off + rank] = n;
        }
        off += __popc(mk);
    }
    __syncthreads();

    int cnt = woff[7] + wcount[7];
    int npairs = (cnt + 1) >> 1;
    if (npairs > MAXP) npairs = MAXP;
    if (threadIdx.x == 0) g_cellPairCount[cell] = npairs;

    for (int j = threadIdx.x; j < npairs; j += 256) {
        int n0 = list[2 * j];
        float4 q0a = g_q0[n0], q1a = g_q1[n0];
        float4 q0b, q1b;
        if (2 * j + 1 < cnt) {
            int n1 = list[2 * j + 1];
            q0b = g_q0[n1];
            q1b = g_q1[n1];
        } else {
            q0b = make_float4(0.f, 0.f, 0.f, 0.f);
            q1b = make_float4(0.f, 0.f, -1e30f, 0.f);   // exp2(-1e30) = 0
        }
        float4* dst = &g_cellPairs[(cell * MAXP + j) * 4];
        dst[0] = make_float4(q0a.x, q0b.x, q0a.y, q0b.y);   // ax01 | ay01
        dst[1] = make_float4(q0a.z, q0b.z, q0a.w, q0b.w);   // az01 | bx01
        dst[2] = make_float4(q1a.x, q1b.x, q1a.y, q1b.y);   // by01 | bz01
        dst[3] = make_float4(q1a.z, q1b.z, 0.0f, 0.0f);     // cc01
    }
}

// ---------- K3: exclusive scan over cell counts (1 block) ----------
__global__ void scan_kernel() {
    __shared__ int s[NCELLS];
    int t = threadIdx.x;
    int v = g_cellCount[t];
    s[t] = v;
    __syncthreads();
    for (int off = 1; off < NCELLS; off <<= 1) {
        int x = (t >= off) ? s[t - off] : 0;
        __syncthreads();
        s[t] += x;
        __syncthreads();
    }
    g_cellStart[t] = s[t] - v;
}

// ---------- K4: scatter points into cell-sorted order ----------
__global__ void scatter_kernel(int M) {
    int idx = blockIdx.x * blockDim.x + threadIdx.x;
    if (idx < M)
        g_sorted[g_cellStart[g_pCell[idx]] + g_pSlot[idx]] = idx;
}

// ---------- K5: eval ----------
__global__ void __launch_bounds__(EVAL_THREADS)
eval_kernel(const float* __restrict__ points,
            float* __restrict__ out, int M) {
    __shared__ float4 spp[(MAXP / EVAL_SEGS) * 4];   // 16KB
    int cell = blockIdx.x;
    int seg = blockIdx.y;
    int np = g_cellPairCount[cell];
    int cnt = g_cellCount[cell];
    if (cnt == 0 || np == 0) return;
    int half = (np + EVAL_SEGS - 1) / EVAL_SEGS;
    int j0 = seg * half;
    int jcnt = min(np - j0, half);
    if (jcnt <= 0) return;

    const float4* src = &g_cellPairs[(cell * MAXP + j0) * 4];
    for (int i = threadIdx.x; i < jcnt * 4; i += EVAL_THREADS) spp[i] = src[i];
    __syncthreads();

    int start = g_cellStart[cell];
    const ulonglong2* g = (const ulonglong2*)spp;

    for (int base = threadIdx.x; base < cnt; base += EVAL_THREADS) {
        int m = g_sorted[start + base];
        float px = points[3 * m], py = points[3 * m + 1], pz = points[3 * m + 2];

        unsigned long long vxx = pack2(px * px, px * px), vx = pack2(px, px);
        unsigned long long vyy = pack2(py * py, py * py), vy = pack2(py, py);
        unsigned long long vzz = pack2(pz * pz, pz * pz), vz = pack2(pz, pz);

        unsigned long long acc = pack2(0.0f, 0.0f);
#pragma unroll 4
        for (int j = 0; j < jcnt; j++) {
            ulonglong2 u0 = g[4 * j + 0];    // ax01 | ay01
            ulonglong2 u1 = g[4 * j + 1];    // az01 | bx01
            ulonglong2 u2 = g[4 * j + 2];    // by01 | bz01
            unsigned long long cc01 = *((const unsigned long long*)(g + 4 * j + 3));

            unsigned long long r = ffma2(u0.x, vxx, cc01);
            r = ffma2(u0.y, vyy, r);
            r = ffma2(u1.x, vzz, r);
            r = ffma2(u1.y, vx,  r);
            r = ffma2(u2.x, vy,  r);
            r = ffma2(u2.y, vz,  r);

            float lo, hi;
            unpack2(r, lo, hi);
            acc = addx2(acc, pack2(ex2(lo), ex2(hi)));
        }
        atomicAdd(&out[m], pair_hsum(acc));
    }
}

extern "C" void kernel_launch(void* const* d_in, const int* in_sizes, int n_in,
                              void* d_out, int out_size) {
    const float* points      = (const float*)d_in[0];  // [M,3]
    const float* positions   = (const float*)d_in[1];  // [N,3]
    const float* log_scales  = (const float*)d_in[2];  // [N,3]
    const float* intensities = (const float*)d_in[3];  // [N]
    float* out = (float*)d_out;

    int M = in_sizes[0] / 3;
    int N = in_sizes[3];

    void* ccPtr = nullptr;
    cudaGetSymbolAddress(&ccPtr, g_cellCount);
    cudaMemsetAsync(ccPtr, 0, NCELLS * sizeof(int));

    int mx = (M > N) ? M : N;
    prep_kernel<<<(mx + 255) / 256, 256>>>(points, positions, log_scales,
                                           intensities, out, M, N);
    build_lists<<<NCELLS, 256>>>(positions, N);
    scan_kernel<<<1, NCELLS>>>();
    scatter_kernel<<<(M + 255) / 256, 256>>>(M);

    dim3 eg(NCELLS, EVAL_SEGS);
    eval_kernel<<<eg, EVAL_THREADS>>>(points, out, M);
}

// round 11
// speedup vs baseline: 1.2099x; 1.2099x over previous
#include <cuda_runtime.h>
#include <cuda_bf16.h>

// values[m] = sum_n exp(-0.5 * sum_d (p[m,d]-pos[n,d])^2 / (exp(ls[n,d])^2+eps)) * I[n]
//
// Log2-domain coefficients per gaussian (see prior rounds) + SPATIAL CULLING:
// 8x8x8 cells over [0,1]^3; gaussian kept for a cell iff its max possible
// log2-contribution over the cell box >= CUT_ARG (-37 -> < 7e-12 dropped).
//
// 4 graph nodes:
//   memset(cell counters, 2KB)
//   prep : coefficients, zero out, bin points (cell id + slot via atomicAdd)
//   mid  : blocks [0,512)   build per-cell pair-packed coefficient lists
//          blocks [512,708) recompute the 512-entry scan locally in smem and
//                           scatter points into cell-sorted float4(px,py,pz,m);
//                           block 512 also publishes g_cellStart
//   eval : grid (512 cells x 2 segs), FFMA2 pair loop over smem-staged
//          culled coefficients, atomicAdd combine.

#define GDIM   8
#define NCELLS (GDIM * GDIM * GDIM)      // 512
#define MAXM   65536
#define MAXNG  2048
#define MAXP   512                       // max pairs per cell
#define CUT_ARG (-37.0f)
#define EVAL_SEGS 2
#define EVAL_THREADS 128

__device__ float4 g_q0[MAXNG];           // (ax, ay, az, bx)
__device__ float4 g_q1[MAXNG];           // (by, bz, cc, log2I)
__device__ int    g_cellCount[NCELLS];
__device__ int    g_cellStart[NCELLS];
__device__ int    g_pCell[MAXM];
__device__ int    g_pSlot[MAXM];
__device__ float4 g_sortedPts[MAXM];     // (px,py,pz, bitcast point index)
__device__ int    g_cellPairCount[NCELLS];
__device__ float4 g_cellPairs[NCELLS * MAXP * 4];

// ---------- packed f32x2 helpers ----------
__device__ __forceinline__ unsigned long long ffma2(unsigned long long a,
                                                    unsigned long long b,
                                                    unsigned long long c) {
    unsigned long long d;
    asm("fma.rn.f32x2 %0, %1, %2, %3;" : "=l"(d) : "l"(a), "l"(b), "l"(c));
    return d;
}
__device__ __forceinline__ unsigned long long addx2(unsigned long long a,
                                                    unsigned long long b) {
    unsigned long long d;
    asm("add.rn.f32x2 %0, %1, %2;" : "=l"(d) : "l"(a), "l"(b));
    return d;
}
__device__ __forceinline__ unsigned long long pack2(float lo, float hi) {
    unsigned long long d;
    asm("mov.b64 %0, {%1, %2};" : "=l"(d) : "f"(lo), "f"(hi));
    return d;
}
__device__ __forceinline__ float pair_hsum(unsigned long long v) {
    float lo, hi;
    asm("mov.b64 {%0, %1}, %2;" : "=f"(lo), "=f"(hi) : "l"(v));
    return lo + hi;
}
__device__ __forceinline__ void unpack2(unsigned long long v, float& lo, float& hi) {
    asm("mov.b64 {%0, %1}, %2;" : "=f"(lo), "=f"(hi) : "l"(v));
}
__device__ __forceinline__ float ex2(float x) {
    float r;
    asm("ex2.approx.f32 %0, %1;" : "=f"(r) : "f"(x));
    return r;
}

// ---------- K1: coefficients + zero out + bin points ----------
__global__ void prep_kernel(const float* __restrict__ points,
                            const float* __restrict__ positions,
                            const float* __restrict__ log_scales,
                            const float* __restrict__ intensities,
                            float* __restrict__ out,
                            int M, int N) {
    int idx = blockIdx.x * blockDim.x + threadIdx.x;
    if (idx < M) {
        out[idx] = 0.0f;
        float px = points[3 * idx], py = points[3 * idx + 1], pz = points[3 * idx + 2];
        int cx = min(GDIM - 1, max(0, (int)(px * GDIM)));
        int cy = min(GDIM - 1, max(0, (int)(py * GDIM)));
        int cz = min(GDIM - 1, max(0, (int)(pz * GDIM)));
        int cell = (cz * GDIM + cy) * GDIM + cx;
        g_pCell[idx] = cell;
        g_pSlot[idx] = atomicAdd(&g_cellCount[cell], 1);
    }
    if (idx < N) {
        const float LOG2E = 1.4426950408889634f;
        float a[3], b[3];
        float c = 0.0f;
#pragma unroll
        for (int d = 0; d < 3; d++) {
            float s = __expf(log_scales[3 * idx + d]);
            float civ = -0.5f * LOG2E / (s * s + 1e-6f);
            float p = positions[3 * idx + d];
            a[d] = civ;
            b[d] = -2.0f * civ * p;
            c = fmaf(civ, p * p, c);
        }
        float logI = __log2f(intensities[idx]);   // I=0 -> -inf -> culled/zero
        g_q0[idx] = make_float4(a[0], a[1], a[2], b[0]);
        g_q1[idx] = make_float4(b[1], b[2], c + logI, logI);
    }
}

// ---------- K2: fused build_lists + scan + scatter ----------
__global__ void __launch_bounds__(256)
mid_kernel(const float* __restrict__ positions,
           const float* __restrict__ points,
           int N, int M) {
    __shared__ int sh[MAXNG];   // reused: gaussian list OR scan buffer

    if (blockIdx.x < NCELLS) {
        // ---- build this cell's culled pair list (deterministic) ----
        __shared__ int wcount[8];
        __shared__ int woff[8];

        int cell = blockIdx.x;
        int cx = cell & (GDIM - 1);
        int cy = (cell >> 3) & (GDIM - 1);
        int cz = cell >> 6;
        const float W = 1.0f / GDIM;
        float lox = cx * W, hix = lox + W;
        float loy = cy * W, hiy = loy + W;
        float loz = cz * W, hiz = loz + W;

        int w = threadIdx.x >> 5;
        int lane = threadIdx.x & 31;
        int numChunks = (N + 31) >> 5;

        unsigned msk[8];
        int cntw = 0;
        int ki = 0;
        for (int c = w; c < numChunks; c += 8, ki++) {
            int n = c * 32 + lane;
            bool keep = false;
            if (n < N) {
                float4 q0 = g_q0[n];
                float logI = g_q1[n].w;
                float sx = positions[3 * n], sy = positions[3 * n + 1], sz = positions[3 * n + 2];
                float ddx = fmaxf(fmaxf(lox - sx, sx - hix), 0.0f);
                float ddy = fmaxf(fmaxf(loy - sy, sy - hiy), 0.0f);
                float ddz = fmaxf(fmaxf(loz - sz, sz - hiz), 0.0f);
                float bound = q0.x * ddx * ddx + q0.y * ddy * ddy + q0.z * ddz * ddz + logI;
                keep = (bound >= CUT_ARG);
            }
            unsigned mk = __ballot_sync(0xffffffffu, keep);
            msk[ki] = mk;
            cntw += __popc(mk);
        }
        if (lane == 0) wcount[w] = cntw;
        __syncthreads();
        if (threadIdx.x == 0) {
            int run = 0;
#pragma unroll
            for (int i = 0; i < 8; i++) { woff[i] = run; run += wcount[i]; }
        }
        __syncthreads();

        int off = woff[w];
        ki = 0;
        for (int c = w; c < numChunks; c += 8, ki++) {
            unsigned mk = msk[ki];
            int n = c * 32 + lane;
            if ((mk >> lane) & 1u) {
                int rank = __popc(mk & ((1u << lane) - 1u));
                sh[off + rank] = n;
            }
            off += __popc(mk);
        }
        __syncthreads();

        int cnt = woff[7] + wcount[7];
        int npairs = (cnt + 1) >> 1;
        if (npairs > MAXP) npairs = MAXP;
        if (threadIdx.x == 0) g_cellPairCount[cell] = npairs;

        for (int j = threadIdx.x; j < npairs; j += 256) {
            int n0 = sh[2 * j];
            float4 q0a = g_q0[n0], q1a = g_q1[n0];
            float4 q0b, q1b;
            if (2 * j + 1 < cnt) {
                int n1 = sh[2 * j + 1];
                q0b = g_q0[n1];
                q1b = g_q1[n1];
            } else {
                q0b = make_float4(0.f, 0.f, 0.f, 0.f);
                q1b = make_float4(0.f, 0.f, -1e30f, 0.f);   // exp2(-1e30) = 0
            }
            float4* dst = &g_cellPairs[(cell * MAXP + j) * 4];
            dst[0] = make_float4(q0a.x, q0b.x, q0a.y, q0b.y);   // ax01 | ay01
            dst[1] = make_float4(q0a.z, q0b.z, q0a.w, q0b.w);   // az01 | bx01
            dst[2] = make_float4(q1a.x, q1b.x, q1a.y, q1b.y);   // by01 | bz01
            dst[3] = make_float4(q1a.z, q1b.z, 0.0f, 0.0f);     // cc01
        }
    } else {
        // ---- local scan of cell counts + scatter this block's points ----
        int t = threadIdx.x;
        sh[t] = g_cellCount[t];
        sh[t + 256] = g_cellCount[t + 256];
        __syncthreads();
        for (int off = 1; off < NCELLS; off <<= 1) {
            int a = (t >= off) ? sh[t - off] : 0;
            int b = (t + 256 >= off) ? sh[t + 256 - off] : 0;
            __syncthreads();
            sh[t] += a;
            sh[t + 256] += b;
            __syncthreads();
        }
        // sh now holds INCLUSIVE scan; start(c) = sh[c] - count(c)

        if (blockIdx.x == NCELLS) {   // publish exclusive scan for eval
            g_cellStart[t] = sh[t] - g_cellCount[t];
            g_cellStart[t + 256] = sh[t + 256] - g_cellCount[t + 256];
        }

        int idx = (blockIdx.x - NCELLS) * 256 + t;
        if (idx < M) {
            int cell = g_pCell[idx];
            int start = sh[cell] - g_cellCount[cell];
            float px = points[3 * idx], py = points[3 * idx + 1], pz = points[3 * idx + 2];
            g_sortedPts[start + g_pSlot[idx]] =
                make_float4(px, py, pz, __int_as_float(idx));
        }
    }
}

// ---------- K3: eval ----------
__global__ void __launch_bounds__(EVAL_THREADS)
eval_kernel(float* __restrict__ out) {
    __shared__ float4 spp[(MAXP / EVAL_SEGS) * 4];   // 16KB
    int cell = blockIdx.x;
    int seg = blockIdx.y;
    int np = g_cellPairCount[cell];
    int cnt = g_cellCount[cell];
    if (cnt == 0 || np == 0) return;
    int half = (np + EVAL_SEGS - 1) / EVAL_SEGS;
    int j0 = seg * half;
    int jcnt = min(np - j0, half);
    if (jcnt <= 0) return;

    const float4* src = &g_cellPairs[(cell * MAXP + j0) * 4];
    for (int i = threadIdx.x; i < jcnt * 4; i += EVAL_THREADS) spp[i] = src[i];
    __syncthreads();

    int start = g_cellStart[cell];
    const ulonglong2* g = (const ulonglong2*)spp;

    for (int base = threadIdx.x; base < cnt; base += EVAL_THREADS) {
        float4 pt = g_sortedPts[start + base];
        float px = pt.x, py = pt.y, pz = pt.z;
        int m = __float_as_int(pt.w);

        unsigned long long vxx = pack2(px * px, px * px), vx = pack2(px, px);
        unsigned long long vyy = pack2(py * py, py * py), vy = pack2(py, py);
        unsigned long long vzz = pack2(pz * pz, pz * pz), vz = pack2(pz, pz);

        unsigned long long acc = pack2(0.0f, 0.0f);
#pragma unroll 4
        for (int j = 0; j < jcnt; j++) {
            ulonglong2 u0 = g[4 * j + 0];    // ax01 | ay01
            ulonglong2 u1 = g[4 * j + 1];    // az01 | bx01
            ulonglong2 u2 = g[4 * j + 2];    // by01 | bz01
            unsigned long long cc01 = *((const unsigned long long*)(g + 4 * j + 3));

            unsigned long long r = ffma2(u0.x, vxx, cc01);
            r = ffma2(u0.y, vyy, r);
            r = ffma2(u1.x, vzz, r);
            r = ffma2(u1.y, vx,  r);
            r = ffma2(u2.x, vy,  r);
            r = ffma2(u2.y, vz,  r);

            float lo, hi;
            unpack2(r, lo, hi);
            acc = addx2(acc, pack2(ex2(lo), ex2(hi)));
        }
        atomicAdd(&out[m], pair_hsum(acc));
    }
}

extern "C" void kernel_launch(void* const* d_in, const int* in_sizes, int n_in,
                              void* d_out, int out_size) {
    const float* points      = (const float*)d_in[0];  // [M,3]
    const float* positions   = (const float*)d_in[1];  // [N,3]
    const float* log_scales  = (const float*)d_in[2];  // [N,3]
    const float* intensities = (const float*)d_in[3];  // [N]
    float* out = (float*)d_out;

    int M = in_sizes[0] / 3;
    int N = in_sizes[3];

    void* ccPtr = nullptr;
    cudaGetSymbolAddress(&ccPtr, g_cellCount);
    cudaMemsetAsync(ccPtr, 0, NCELLS * sizeof(int));

    int mx = (M > N) ? M : N;
    prep_kernel<<<(mx + 255) / 256, 256>>>(points, positions, log_scales,
                                           intensities, out, M, N);

    int scatterBlocks = (M + 255) / 256;
    mid_kernel<<<NCELLS + scatterBlocks, 256>>>(positions, points, N, M);

    dim3 eg(NCELLS, EVAL_SEGS);
    eval_kernel<<<eg, EVAL_THREADS>>>(out);
}

// round 12
// speedup vs baseline: 1.5111x; 1.2490x over previous
#include <cuda_runtime.h>
#include <cuda_bf16.h>

// values[m] = sum_n exp(-0.5 * sum_d (p[m,d]-pos[n,d])^2 / (exp(ls[n,d])^2+eps)) * I[n]
//
// Log2-domain coefficients per gaussian + spatial culling on an 8^3 cell grid:
// gaussian kept for a cell iff max possible log2-contribution over the cell
// box >= CUT_ARG (-37 -> dropped mass < 1024*2^-37 ~ 7e-9 absolute).
//
// 3 graph nodes:
//   memset : g_cellCount (2KB)
//   prep   : coefficients; zero out; bin points via per-block SMEM histogram
//            (local rank), one global atomicAdd per (block,cell) to reserve a
//            base range, then scatter points directly into padded per-cell
//            arrays g_cellPts[cell*CAP + slot] = (px,py,pz,idx).
//   eval   : grid (512 cells x 2 segs). Each block ballot-compacts the kept
//            gaussians for its cell into SMEM, packs its segment's pairs
//            (2 gaussians per f32x2 lane), then runs the FFMA2+ex2 loop over
//            the cell's points; atomicAdd(out[m]) combine (2 commutative adds).

#define GDIM   8
#define NCELLS (GDIM * GDIM * GDIM)      // 512
#define MAXNG  2048
#define CAP    256                       // max points per cell (lambda ~98)
#define CUT_ARG (-37.0f)
#define EVAL_SEGS 2
#define EVAL_THREADS 128
#define MAXP_SEG 256                     // pairs per segment (covers 100% kept)

__device__ float4 g_q0[MAXNG];           // (ax, ay, az, bx)
__device__ float4 g_q1[MAXNG];           // (by, bz, cc, log2I)
__device__ int    g_cellCount[NCELLS];
__device__ float4 g_cellPts[NCELLS * CAP];   // (px,py,pz, bitcast point idx)

// ---------- packed f32x2 helpers ----------
__device__ __forceinline__ unsigned long long ffma2(unsigned long long a,
                                                    unsigned long long b,
                                                    unsigned long long c) {
    unsigned long long d;
    asm("fma.rn.f32x2 %0, %1, %2, %3;" : "=l"(d) : "l"(a), "l"(b), "l"(c));
    return d;
}
__device__ __forceinline__ unsigned long long addx2(unsigned long long a,
                                                    unsigned long long b) {
    unsigned long long d;
    asm("add.rn.f32x2 %0, %1, %2;" : "=l"(d) : "l"(a), "l"(b));
    return d;
}
__device__ __forceinline__ unsigned long long pack2(float lo, float hi) {
    unsigned long long d;
    asm("mov.b64 %0, {%1, %2};" : "=l"(d) : "f"(lo), "f"(hi));
    return d;
}
__device__ __forceinline__ float pair_hsum(unsigned long long v) {
    float lo, hi;
    asm("mov.b64 {%0, %1}, %2;" : "=f"(lo), "=f"(hi) : "l"(v));
    return lo + hi;
}
__device__ __forceinline__ void unpack2(unsigned long long v, float& lo, float& hi) {
    asm("mov.b64 {%0, %1}, %2;" : "=f"(lo), "=f"(hi) : "l"(v));
}
__device__ __forceinline__ float ex2(float x) {
    float r;
    asm("ex2.approx.f32 %0, %1;" : "=f"(r) : "f"(x));
    return r;
}

// ---------- K1: coefficients + zero out + bin & scatter points ----------
__global__ void __launch_bounds__(256)
prep_kernel(const float* __restrict__ points,
            const float* __restrict__ positions,
            const float* __restrict__ log_scales,
            const float* __restrict__ intensities,
            float* __restrict__ out,
            int M, int N) {
    __shared__ int hist[NCELLS];
    __shared__ int sbase[NCELLS];
    int t = threadIdx.x;
    hist[t] = 0;
    hist[t + 256] = 0;
    __syncthreads();

    int idx = blockIdx.x * 256 + t;

    float px = 0.f, py = 0.f, pz = 0.f;
    int cell = -1, rank = 0;
    if (idx < M) {
        out[idx] = 0.0f;
        px = points[3 * idx];
        py = points[3 * idx + 1];
        pz = points[3 * idx + 2];
        int cx = min(GDIM - 1, max(0, (int)(px * GDIM)));
        int cy = min(GDIM - 1, max(0, (int)(py * GDIM)));
        int cz = min(GDIM - 1, max(0, (int)(pz * GDIM)));
        cell = (cz * GDIM + cy) * GDIM + cx;
        rank = atomicAdd(&hist[cell], 1);
    }

    // coefficients (independent of binning)
    if (idx < N) {
        const float LOG2E = 1.4426950408889634f;
        float a[3], b[3];
        float c = 0.0f;
#pragma unroll
        for (int d = 0; d < 3; d++) {
            float s = __expf(log_scales[3 * idx + d]);
            float civ = -0.5f * LOG2E / (s * s + 1e-6f);
            float p = positions[3 * idx + d];
            a[d] = civ;
            b[d] = -2.0f * civ * p;
            c = fmaf(civ, p * p, c);
        }
        float logI = __log2f(intensities[idx]);   // I=0 -> -inf -> fully culled
        g_q0[idx] = make_float4(a[0], a[1], a[2], b[0]);
        g_q1[idx] = make_float4(b[1], b[2], c + logI, logI);
    }
    __syncthreads();

    // reserve base ranges: one global atomic per (block, nonempty cell)
#pragma unroll
    for (int k = 0; k < 2; k++) {
        int c = t + k * 256;
        int h = hist[c];
        if (h > 0) sbase[c] = atomicAdd(&g_cellCount[c], h);
    }
    __syncthreads();

    if (idx < M) {
        int slot = sbase[cell] + rank;
        g_cellPts[cell * CAP + slot] = make_float4(px, py, pz, __int_as_float(idx));
    }
}

// ---------- K2: per-cell cull + pack + eval ----------
__global__ void __launch_bounds__(EVAL_THREADS)
eval_kernel(const float* __restrict__ positions,
            float* __restrict__ out, int N) {
    __shared__ int list[MAXNG];                 // kept gaussian ids (8KB)
    __shared__ float4 pairSm[MAXP_SEG * 4];     // packed pair coeffs (16KB)
    __shared__ int wcount[4];
    __shared__ int woff[4];

    int cell = blockIdx.x;
    int seg = blockIdx.y;
    int cnt = g_cellCount[cell];

    int cx = cell & (GDIM - 1);
    int cy = (cell >> 3) & (GDIM - 1);
    int cz = cell >> 6;
    const float W = 1.0f / GDIM;
    float lox = cx * W, hix = lox + W;
    float loy = cy * W, hiy = loy + W;
    float loz = cz * W, hiz = loz + W;

    int w = threadIdx.x >> 5;
    int lane = threadIdx.x & 31;
    int numChunks = (N + 31) >> 5;

    // ---- ballot-compact kept gaussians (deterministic order) ----
    unsigned msk[16];
    int cntw = 0;
    int ki = 0;
    for (int c = w; c < numChunks; c += 4, ki++) {
        int n = c * 32 + lane;
        bool keep = false;
        if (n < N) {
            float4 q0 = g_q0[n];
            float logI = g_q1[n].w;
            float sx = positions[3 * n], sy = positions[3 * n + 1], sz = positions[3 * n + 2];
            float ddx = fmaxf(fmaxf(lox - sx, sx - hix), 0.0f);
            float ddy = fmaxf(fmaxf(loy - sy, sy - hiy), 0.0f);
            float ddz = fmaxf(fmaxf(loz - sz, sz - hiz), 0.0f);
            float bound = q0.x * ddx * ddx + q0.y * ddy * ddy + q0.z * ddz * ddz + logI;
            keep = (bound >= CUT_ARG);
        }
        unsigned mk = __ballot_sync(0xffffffffu, keep);
        msk[ki] = mk;
        cntw += __popc(mk);
    }
    if (lane == 0) wcount[w] = cntw;
    __syncthreads();
    if (threadIdx.x == 0) {
        int run = 0;
#pragma unroll
        for (int i = 0; i < 4; i++) { woff[i] = run; run += wcount[i]; }
    }
    __syncthreads();

    int off = woff[w];
    ki = 0;
    for (int c = w; c < numChunks; c += 4, ki++) {
        unsigned mk = msk[ki];
        int n = c * 32 + lane;
        if ((mk >> lane) & 1u) {
            int r = __popc(mk & ((1u << lane) - 1u));
            list[off + r] = n;
        }
        off += __popc(mk);
    }
    __syncthreads();

    int kept = woff[3] + wcount[3];
    int npairs = (kept + 1) >> 1;
    int half = (npairs + EVAL_SEGS - 1) / EVAL_SEGS;
    int j0 = seg * half;
    int jcnt = min(npairs - j0, half);
    if (jcnt <= 0 || cnt == 0) return;

    // ---- pack this segment's pairs into smem ----
    for (int j2 = threadIdx.x; j2 < jcnt; j2 += EVAL_THREADS) {
        int j = j0 + j2;
        int n0 = list[2 * j];
        float4 q0a = g_q0[n0], q1a = g_q1[n0];
        float4 q0b, q1b;
        if (2 * j + 1 < kept) {
            int n1 = list[2 * j + 1];
            q0b = g_q0[n1];
            q1b = g_q1[n1];
        } else {
            q0b = make_float4(0.f, 0.f, 0.f, 0.f);
            q1b = make_float4(0.f, 0.f, -1e30f, 0.f);   // exp2(-1e30)=0
        }
        pairSm[4 * j2 + 0] = make_float4(q0a.x, q0b.x, q0a.y, q0b.y);  // ax01|ay01
        pairSm[4 * j2 + 1] = make_float4(q0a.z, q0b.z, q0a.w, q0b.w);  // az01|bx01
        pairSm[4 * j2 + 2] = make_float4(q1a.x, q1b.x, q1a.y, q1b.y);  // by01|bz01
        pairSm[4 * j2 + 3] = make_float4(q1a.z, q1b.z, 0.0f, 0.0f);    // cc01
    }
    __syncthreads();

    // ---- eval this cell's points ----
    const ulonglong2* g = (const ulonglong2*)pairSm;
    const float4* pts = &g_cellPts[cell * CAP];

    for (int base = threadIdx.x; base < cnt; base += EVAL_THREADS) {
        float4 pt = pts[base];
        float px = pt.x, py = pt.y, pz = pt.z;
        int m = __float_as_int(pt.w);

        unsigned long long vxx = pack2(px * px, px * px), vx = pack2(px, px);
        unsigned long long vyy = pack2(py * py, py * py), vy = pack2(py, py);
        unsigned long long vzz = pack2(pz * pz, pz * pz), vz = pack2(pz, pz);

        unsigned long long acc = pack2(0.0f, 0.0f);
#pragma unroll 4
        for (int j = 0; j < jcnt; j++) {
            ulonglong2 u0 = g[4 * j + 0];
            ulonglong2 u1 = g[4 * j + 1];
            ulonglong2 u2 = g[4 * j + 2];
            unsigned long long cc01 = *((const unsigned long long*)(g + 4 * j + 3));

            unsigned long long r = ffma2(u0.x, vxx, cc01);
            r = ffma2(u0.y, vyy, r);
            r = ffma2(u1.x, vzz, r);
            r = ffma2(u1.y, vx,  r);
            r = ffma2(u2.x, vy,  r);
            r = ffma2(u2.y, vz,  r);

            float lo, hi;
            unpack2(r, lo, hi);
            acc = addx2(acc, pack2(ex2(lo), ex2(hi)));
        }
        atomicAdd(&out[m], pair_hsum(acc));
    }
}

extern "C" void kernel_launch(void* const* d_in, const int* in_sizes, int n_in,
                              void* d_out, int out_size) {
    const float* points      = (const float*)d_in[0];  // [M,3]
    const float* positions   = (const float*)d_in[1];  // [N,3]
    const float* log_scales  = (const float*)d_in[2];  // [N,3]
    const float* intensities = (const float*)d_in[3];  // [N]
    float* out = (float*)d_out;

    int M = in_sizes[0] / 3;
    int N = in_sizes[3];

    void* ccPtr = nullptr;
    cudaGetSymbolAddress(&ccPtr, g_cellCount);
    cudaMemsetAsync(ccPtr, 0, NCELLS * sizeof(int));

    int prepBlocks = (M + 255) / 256;
    if (prepBlocks * 256 < N) prepBlocks = (N + 255) / 256;
    prep_kernel<<<prepBlocks, 256>>>(points, positions, log_scales,
                                     intensities, out, M, N);

    dim3 eg(NCELLS, EVAL_SEGS);
    eval_kernel<<<eg, EVAL_THREADS>>>(positions, out, N);
}

// round 13
// speedup vs baseline: 1.6686x; 1.1042x over previous
#include <cuda_runtime.h>
#include <cuda_bf16.h>

// values[m] = sum_n exp(-0.5 * sum_d (p[m,d]-pos[n,d])^2 / (exp(ls[n,d])^2+eps)) * I[n]
//
// Log2-domain coefficients per gaussian + spatial culling on an 8^3 cell grid:
// gaussian kept for a cell iff max possible log2-contribution over the cell
// box >= CUT_ARG (-37 -> dropped mass < 1024*2^-37 ~ 7e-9 absolute).
//
// 3 graph nodes:
//   memset : g_cellCount (2KB)
//   prep   : coefficients; zero out; bin points via SMEM histogram + one
//            global atomicAdd per (block,cell); scatter into g_cellPts.
//   eval   : grid (512 cells x 2 segs). Seg s culls ONLY gaussians
//            [s*N/2,(s+1)*N/2) (no duplicated cull work), packs its kept
//            pairs (2 gaussians per f32x2 lane) into SMEM, then evals the
//            cell's points with TWO independent FFMA2+ex2 chains (ILP=2)
//            over pair halves; atomicAdd(out[m]) combine.

#define GDIM   8
#define NCELLS (GDIM * GDIM * GDIM)      // 512
#define MAXNG  2048
#define CAP    256                       // max points per cell (lambda ~98)
#define CUT_ARG (-37.0f)
#define EVAL_SEGS 2
#define EVAL_THREADS 128
#define MAXP_SEG 256                     // max pairs per half-list (covers all)

__device__ float4 g_q0[MAXNG];           // (ax, ay, az, bx)
__device__ float4 g_q1[MAXNG];           // (by, bz, cc, log2I)
__device__ int    g_cellCount[NCELLS];
__device__ float4 g_cellPts[NCELLS * CAP];   // (px,py,pz, bitcast point idx)

// ---------- packed f32x2 helpers ----------
__device__ __forceinline__ unsigned long long ffma2(unsigned long long a,
                                                    unsigned long long b,
                                                    unsigned long long c) {
    unsigned long long d;
    asm("fma.rn.f32x2 %0, %1, %2, %3;" : "=l"(d) : "l"(a), "l"(b), "l"(c));
    return d;
}
__device__ __forceinline__ unsigned long long addx2(unsigned long long a,
                                                    unsigned long long b) {
    unsigned long long d;
    asm("add.rn.f32x2 %0, %1, %2;" : "=l"(d) : "l"(a), "l"(b));
    return d;
}
__device__ __forceinline__ unsigned long long pack2(float lo, float hi) {
    unsigned long long d;
    asm("mov.b64 %0, {%1, %2};" : "=l"(d) : "f"(lo), "f"(hi));
    return d;
}
__device__ __forceinline__ float pair_hsum(unsigned long long v) {
    float lo, hi;
    asm("mov.b64 {%0, %1}, %2;" : "=f"(lo), "=f"(hi) : "l"(v));
    return lo + hi;
}
__device__ __forceinline__ void unpack2(unsigned long long v, float& lo, float& hi) {
    asm("mov.b64 {%0, %1}, %2;" : "=f"(lo), "=f"(hi) : "l"(v));
}
__device__ __forceinline__ float ex2(float x) {
    float r;
    asm("ex2.approx.f32 %0, %1;" : "=f"(r) : "f"(x));
    return r;
}

// ---------- K1: coefficients + zero out + bin & scatter points ----------
__global__ void __launch_bounds__(256)
prep_kernel(const float* __restrict__ points,
            const float* __restrict__ positions,
            const float* __restrict__ log_scales,
            const float* __restrict__ intensities,
            float* __restrict__ out,
            int M, int N) {
    __shared__ int hist[NCELLS];
    __shared__ int sbase[NCELLS];
    int t = threadIdx.x;
    hist[t] = 0;
    hist[t + 256] = 0;
    __syncthreads();

    int idx = blockIdx.x * 256 + t;

    float px = 0.f, py = 0.f, pz = 0.f;
    int cell = -1, rank = 0;
    if (idx < M) {
        out[idx] = 0.0f;
        px = points[3 * idx];
        py = points[3 * idx + 1];
        pz = points[3 * idx + 2];
        int cx = min(GDIM - 1, max(0, (int)(px * GDIM)));
        int cy = min(GDIM - 1, max(0, (int)(py * GDIM)));
        int cz = min(GDIM - 1, max(0, (int)(pz * GDIM)));
        cell = (cz * GDIM + cy) * GDIM + cx;
        rank = atomicAdd(&hist[cell], 1);
    }

    if (idx < N) {
        const float LOG2E = 1.4426950408889634f;
        float a[3], b[3];
        float c = 0.0f;
#pragma unroll
        for (int d = 0; d < 3; d++) {
            float s = __expf(log_scales[3 * idx + d]);
            float civ = -0.5f * LOG2E / (s * s + 1e-6f);
            float p = positions[3 * idx + d];
            a[d] = civ;
            b[d] = -2.0f * civ * p;
            c = fmaf(civ, p * p, c);
        }
        float logI = __log2f(intensities[idx]);   // I=0 -> -inf -> fully culled
        g_q0[idx] = make_float4(a[0], a[1], a[2], b[0]);
        g_q1[idx] = make_float4(b[1], b[2], c + logI, logI);
    }
    __syncthreads();

#pragma unroll
    for (int k = 0; k < 2; k++) {
        int c = t + k * 256;
        int h = hist[c];
        if (h > 0) sbase[c] = atomicAdd(&g_cellCount[c], h);
    }
    __syncthreads();

    if (idx < M) {
        int slot = sbase[cell] + rank;
        g_cellPts[cell * CAP + slot] = make_float4(px, py, pz, __int_as_float(idx));
    }
}

// ---------- K2: per-cell half-list cull + pack + ILP-2 eval ----------
__global__ void __launch_bounds__(EVAL_THREADS)
eval_kernel(const float* __restrict__ positions,
            float* __restrict__ out, int N) {
    __shared__ int list[MAXNG / 2 + 32];        // kept ids in this half (~2KB)
    __shared__ float4 pairSm[MAXP_SEG * 4];     // packed pair coeffs (16KB)
    __shared__ int wcount[4];
    __shared__ int woff[4];

    int cell = blockIdx.x;
    int seg = blockIdx.y;
    int cnt = g_cellCount[cell];

    int cx = cell & (GDIM - 1);
    int cy = (cell >> 3) & (GDIM - 1);
    int cz = cell >> 6;
    const float W = 1.0f / GDIM;
    float lox = cx * W, hix = lox + W;
    float loy = cy * W, hiy = loy + W;
    float loz = cz * W, hiz = loz + W;

    int w = threadIdx.x >> 5;
    int lane = threadIdx.x & 31;
    int halfN = N / 2;
    int nBase = seg * halfN;
    int numChunks = (halfN + 31) >> 5;          // 16 @ N=1024

    // ---- ballot-compact kept gaussians in THIS HALF (deterministic) ----
    unsigned msk[8];
    int cntw = 0;
    int ki = 0;
    for (int c = w; c < numChunks; c += 4, ki++) {
        int n = nBase + c * 32 + lane;
        bool keep = false;
        if (n < nBase + halfN) {
            float4 q0 = g_q0[n];
            float logI = g_q1[n].w;
            float sx = positions[3 * n], sy = positions[3 * n + 1], sz = positions[3 * n + 2];
            float ddx = fmaxf(fmaxf(lox - sx, sx - hix), 0.0f);
            float ddy = fmaxf(fmaxf(loy - sy, sy - hiy), 0.0f);
            float ddz = fmaxf(fmaxf(loz - sz, sz - hiz), 0.0f);
            float bound = q0.x * ddx * ddx + q0.y * ddy * ddy + q0.z * ddz * ddz + logI;
            keep = (bound >= CUT_ARG);
        }
        unsigned mk = __ballot_sync(0xffffffffu, keep);
        msk[ki] = mk;
        cntw += __popc(mk);
    }
    if (lane == 0) wcount[w] = cntw;
    __syncthreads();
    if (threadIdx.x == 0) {
        int run = 0;
#pragma unroll
        for (int i = 0; i < 4; i++) { woff[i] = run; run += wcount[i]; }
    }
    __syncthreads();

    int off = woff[w];
    ki = 0;
    for (int c = w; c < numChunks; c += 4, ki++) {
        unsigned mk = msk[ki];
        int n = nBase + c * 32 + lane;
        if ((mk >> lane) & 1u) {
            int r = __popc(mk & ((1u << lane) - 1u));
            list[off + r] = n;
        }
        off += __popc(mk);
    }
    __syncthreads();

    int kept = woff[3] + wcount[3];
    int jcnt = (kept + 1) >> 1;
    if (jcnt > MAXP_SEG) jcnt = MAXP_SEG;
    if (jcnt <= 0 || cnt == 0) return;

    // ---- pack pairs into smem ----
    for (int j = threadIdx.x; j < jcnt; j += EVAL_THREADS) {
        int n0 = list[2 * j];
        float4 q0a = g_q0[n0], q1a = g_q1[n0];
        float4 q0b, q1b;
        if (2 * j + 1 < kept) {
            int n1 = list[2 * j + 1];
            q0b = g_q0[n1];
            q1b = g_q1[n1];
        } else {
            q0b = make_float4(0.f, 0.f, 0.f, 0.f);
            q1b = make_float4(0.f, 0.f, -1e30f, 0.f);   // exp2(-1e30)=0
        }
        pairSm[4 * j + 0] = make_float4(q0a.x, q0b.x, q0a.y, q0b.y);  // ax01|ay01
        pairSm[4 * j + 1] = make_float4(q0a.z, q0b.z, q0a.w, q0b.w);  // az01|bx01
        pairSm[4 * j + 2] = make_float4(q1a.x, q1b.x, q1a.y, q1b.y);  // by01|bz01
        pairSm[4 * j + 3] = make_float4(q1a.z, q1b.z, 0.0f, 0.0f);    // cc01
    }
    __syncthreads();

    // ---- eval: ILP=2 over pair halves ----
    const ulonglong2* g = (const ulonglong2*)pairSm;
    const float4* pts = &g_cellPts[cell * CAP];
    int jh = jcnt >> 1;
    const ulonglong2* gB = g + (size_t)jh * 4;

    for (int base = threadIdx.x; base < cnt; base += EVAL_THREADS) {
        float4 pt = pts[base];
        float px = pt.x, py = pt.y, pz = pt.z;
        int m = __float_as_int(pt.w);

        unsigned long long vxx = pack2(px * px, px * px), vx = pack2(px, px);
        unsigned long long vyy = pack2(py * py, py * py), vy = pack2(py, py);
        unsigned long long vzz = pack2(pz * pz, pz * pz), vz = pack2(pz, pz);

        unsigned long long accA = pack2(0.0f, 0.0f);
        unsigned long long accB = pack2(0.0f, 0.0f);

#pragma unroll 4
        for (int j = 0; j < jh; j++) {
            ulonglong2 a0 = g[4 * j + 0];
            ulonglong2 a1 = g[4 * j + 1];
            ulonglong2 a2 = g[4 * j + 2];
            unsigned long long ccA = *((const unsigned long long*)(g + 4 * j + 3));
            ulonglong2 b0 = gB[4 * j + 0];
            ulonglong2 b1 = gB[4 * j + 1];
            ulonglong2 b2 = gB[4 * j + 2];
            unsigned long long ccB = *((const unsigned long long*)(gB + 4 * j + 3));

            unsigned long long rA = ffma2(a0.x, vxx, ccA);
            unsigned long long rB = ffma2(b0.x, vxx, ccB);
            rA = ffma2(a0.y, vyy, rA);
            rB = ffma2(b0.y, vyy, rB);
            rA = ffma2(a1.x, vzz, rA);
            rB = ffma2(b1.x, vzz, rB);
            rA = ffma2(a1.y, vx,  rA);
            rB = ffma2(b1.y, vx,  rB);
            rA = ffma2(a2.x, vy,  rA);
            rB = ffma2(b2.x, vy,  rB);
            rA = ffma2(a2.y, vz,  rA);
            rB = ffma2(b2.y, vz,  rB);

            float loA, hiA, loB, hiB;
            unpack2(rA, loA, hiA);
            unpack2(rB, loB, hiB);
            accA = addx2(accA, pack2(ex2(loA), ex2(hiA)));
            accB = addx2(accB, pack2(ex2(loB), ex2(hiB)));
        }
        if (jcnt & 1) {   // tail pair
            int j = jcnt - 1;
            ulonglong2 a0 = g[4 * j + 0];
            ulonglong2 a1 = g[4 * j + 1];
            ulonglong2 a2 = g[4 * j + 2];
            unsigned long long ccA = *((const unsigned long long*)(g + 4 * j + 3));
            unsigned long long rA = ffma2(a0.x, vxx, ccA);
            rA = ffma2(a0.y, vyy, rA);
            rA = ffma2(a1.x, vzz, rA);
            rA = ffma2(a1.y, vx,  rA);
            rA = ffma2(a2.x, vy,  rA);
            rA = ffma2(a2.y, vz,  rA);
            float lo, hi;
            unpack2(rA, lo, hi);
            accA = addx2(accA, pack2(ex2(lo), ex2(hi)));
        }

        atomicAdd(&out[m], pair_hsum(addx2(accA, accB)));
    }
}

extern "C" void kernel_launch(void* const* d_in, const int* in_sizes, int n_in,
                              void* d_out, int out_size) {
    const float* points      = (const float*)d_in[0];  // [M,3]
    const float* positions   = (const float*)d_in[1];  // [N,3]
    const float* log_scales  = (const float*)d_in[2];  // [N,3]
    const float* intensities = (const float*)d_in[3];  // [N]
    float* out = (float*)d_out;

    int M = in_sizes[0] / 3;
    int N = in_sizes[3];

    void* ccPtr = nullptr;
    cudaGetSymbolAddress(&ccPtr, g_cellCount);
    cudaMemsetAsync(ccPtr, 0, NCELLS * sizeof(int));

    int prepBlocks = (M + 255) / 256;
    if (prepBlocks * 256 < N) prepBlocks = (N + 255) / 256;
    prep_kernel<<<prepBlocks, 256>>>(points, positions, log_scales,
                                     intensities, out, M, N);

    dim3 eg(NCELLS, EVAL_SEGS);
    eval_kernel<<<eg, EVAL_THREADS>>>(positions, out, N);
}